// round 14
// baseline (speedup 1.0000x reference)
#include <cuda_runtime.h>
#include <cuda_bf16.h>

// Problem constants (match reference_code)
#define BB   32
#define LL   4096
#define CC   128
#define CS   128            // chunk size along L
#define NCH  (LL / CS)      // 32 chunks per batch
#define NCARRY (NCH - 1)    // carries actually consumed (last chunk's is dead)
#define OUTW (2 * CC + 1)   // 257 output features
#define TROWS 16            // output rows staged in smem per flush

// Scratch: end-of-chunk carry states for chunks 0..NCARRY-1
// (phase1 writes local, phase2 converts to full prefix in place)
__device__ float g_cP[BB * NCARRY * CC];   // one-hot EMA state per channel
__device__ float g_cA[BB * NCARRY * CC];   // amount*one-hot EMA state per channel
__device__ float g_cD[BB * NCARRY];        // delta EMA state

// ---------------------------------------------------------------------------
// Phase 1: per-chunk local recurrence from zero init (chunk 0: exact init).
// Grid (NCARRY, BB), 128 threads (one channel per thread). The last chunk's
// carry is never consumed, so it is not computed.
// Bit-faithful to the reference's iterated recurrence within the chunk.
// NOTE: no prob-sum state — fmaf(0.9f, 1.0f, 0.1f) rounds to exactly 1.0f,
// so the explicit sum-EMA is the constant 1.0 and normalization is a no-op;
// the reference's channel-sum drifts <= ~6e-7 from 1.0 (1000x under 1e-3).
// ---------------------------------------------------------------------------
__global__ __launch_bounds__(CC) void phase1_kernel(
    const float* __restrict__ ts,
    const int*   __restrict__ labels,
    const float* __restrict__ amounts)
{
    const int b  = blockIdx.y;
    const int ch = blockIdx.x;
    const int c  = threadIdx.x;

    __shared__ int   slab[CS];
    __shared__ float samt[CS];
    __shared__ float sdel[CS];

    const int gl = b * LL + ch * CS + c;
    slab[c] = labels[gl];
    samt[c] = amounts[gl];
    float t = ts[gl];
    float del = 0.f;
    if (!(ch == 0 && c == 0)) {           // guard avoids OOB read at global l==0
        del = fminf(t - ts[gl - 1], 100.0f);
    }
    sdel[c] = del;
    __syncthreads();

    float p = 0.f, a = 0.f, d = 0.f;
    int l0 = 0;
    if (ch == 0) {
        // exact init: y[0] = x[0]
        const int   lab = slab[0];
        const float oh  = (lab == c) ? 1.0f : 0.0f;
        p = oh;
        a = samt[0] * oh;
        d = 0.0f;
        l0 = 1;
    }

    #pragma unroll 4
    for (int l = l0; l < CS; l++) {
        const int   lab  = slab[l];
        const float incp = (lab == c) ? 0.1f : 0.0f;
        p = fmaf(0.9f, p, incp);
        a = fmaf(0.9f, a, incp * samt[l]);
        d = fmaf(0.9f, d, 0.1f * sdel[l]);
    }

    const int idx = b * NCARRY + ch;
    g_cP[idx * CC + c] = p;
    g_cA[idx * CC + c] = a;
    if (c == 0) {
        g_cD[idx] = d;
    }
}

// ---------------------------------------------------------------------------
// Phase 2: convert chunk-local states to full prefix states (in place).
// full[k] = m^CS * full[k-1] + local[k].  Grid BB, 128 threads.
// Interleaved load-all first (62 independent LDGs -> MLP hides one DRAM
// latency), then the 31-step FMA chain (4 cyc/step), then store-all.
// Avoids the serialized ~31 x 600-cycle dependent-load chain of the naive
// in-place loop.
// ---------------------------------------------------------------------------
__global__ __launch_bounds__(CC) void phase2_kernel(float m128)
{
    const int b = blockIdx.x;
    const int c = threadIdx.x;
    const int base = b * NCARRY;

    float vP[NCARRY], vA[NCARRY];
    #pragma unroll
    for (int k = 0; k < NCARRY; k++) {
        const int i = (base + k) * CC + c;
        vP[k] = g_cP[i];
        vA[k] = g_cA[i];
    }
    #pragma unroll
    for (int k = 1; k < NCARRY; k++) {
        vP[k] = fmaf(m128, vP[k - 1], vP[k]);
        vA[k] = fmaf(m128, vA[k - 1], vA[k]);
    }
    #pragma unroll
    for (int k = 1; k < NCARRY; k++) {
        const int i = (base + k) * CC + c;
        g_cP[i] = vP[k];
        g_cA[i] = vA[k];
    }

    if (c == 0) {
        float vD[NCARRY];
        #pragma unroll
        for (int k = 0; k < NCARRY; k++) vD[k] = g_cD[base + k];
        #pragma unroll
        for (int k = 1; k < NCARRY; k++) vD[k] = fmaf(m128, vD[k - 1], vD[k]);
        #pragma unroll
        for (int k = 1; k < NCARRY; k++) g_cD[base + k] = vD[k];
    }
}

// ---------------------------------------------------------------------------
// Phase 3: per-chunk recurrence seeded with the exact carry; emit all outputs.
// probs emitted unnormalized (division by the sum-EMA == 1.0f is a no-op);
// amt = a / max(p, 1e-6) -> single MUFU.RCP per thread-step.
// Outputs staged in smem TROWS-row tiles, flushed as float4 (STG.128): chunk
// base is 128*257*4 B = 131584 B (mod 16 == 0) and each 16-row tile is
// 16448 B (mod 16 == 0), so alignment holds despite the odd 257-float row.
// Grid (NCH, BB), 128 threads. Store-bound by design (~17 us DRAM floor).
// ---------------------------------------------------------------------------
__global__ __launch_bounds__(CC) void phase3_kernel(
    const float* __restrict__ ts,
    const int*   __restrict__ labels,
    const float* __restrict__ amounts,
    float*       __restrict__ out)
{
    const int b  = blockIdx.y;
    const int ch = blockIdx.x;
    const int c  = threadIdx.x;

    __shared__ int   slab[CS];
    __shared__ float samt[CS];
    __shared__ float sdel[CS];
    __shared__ __align__(16) float stile[TROWS * OUTW];  // 16*257 floats = 16448 B

    const int gl = b * LL + ch * CS + c;
    slab[c] = labels[gl];
    samt[c] = amounts[gl];
    float t = ts[gl];
    float del = 0.f;
    if (!(ch == 0 && c == 0)) {
        del = fminf(t - ts[gl - 1], 100.0f);
    }
    sdel[c] = del;

    float p, a, d;
    if (ch == 0) {
        p = 0.f; a = 0.f; d = 0.f;
    } else {
        const int idx = b * NCARRY + ch - 1;  // full state at end of previous chunk
        p = g_cP[idx * CC + c];
        a = g_cA[idx * CC + c];
        d = g_cD[idx];
    }
    __syncthreads();

    float* ob = out + (size_t)(b * LL + ch * CS) * OUTW;
    const bool first_chunk = (ch == 0);

    for (int t0 = 0; t0 < CS; t0 += TROWS) {
        // compute TROWS steps into the smem tile
        #pragma unroll 4
        for (int l = t0; l < t0 + TROWS; l++) {
            if (first_chunk && l == 0) {
                // exact init: y[0] = x[0]
                const int   lab = slab[0];
                const float oh  = (lab == c) ? 1.0f : 0.0f;
                p = oh;
                a = samt[0] * oh;
                d = 0.0f;
            } else {
                const int   lab  = slab[l];
                const float incp = (lab == c) ? 0.1f : 0.0f;
                p = fmaf(0.9f, p, incp);
                a = fmaf(0.9f, a, incp * samt[l]);
                d = fmaf(0.9f, d, 0.1f * sdel[l]);
            }
            const float ao = __fdividef(a, fmaxf(p, 1e-6f));
            float* row = stile + (l - t0) * OUTW;
            row[1 + c]      = p;     // normalized prob == p (sum == 1)
            row[1 + CC + c] = ao;
            if (c == 0) row[0] = d;
        }
        __syncthreads();

        // flush tile: TROWS*OUTW floats = 1028 float4s, contiguous & 16B-aligned
        {
            const float4* src = (const float4*)stile;
            float4* dst = (float4*)(ob + (size_t)t0 * OUTW);
            #pragma unroll
            for (int i = c; i < (TROWS * OUTW) / 4; i += CC) {
                dst[i] = src[i];
            }
        }
        __syncthreads();
    }
}

// ---------------------------------------------------------------------------
// Launch: three dependent kernels on the capture stream. No allocs, no syncs.
// ---------------------------------------------------------------------------
extern "C" void kernel_launch(void* const* d_in, const int* in_sizes, int n_in,
                              void* d_out, int out_size)
{
    const float* ts      = (const float*)d_in[0];
    const int*   labels  = (const int*)  d_in[1];
    const float* amounts = (const float*)d_in[2];
    float*       out     = (float*)d_out;

    // m^CS computed in double on host (deterministic)
    double x = 1.0;
    for (int i = 0; i < CS; i++) x *= 0.9;
    const float m128 = (float)x;

    phase1_kernel<<<dim3(NCARRY, BB), CC>>>(ts, labels, amounts);
    phase2_kernel<<<BB, CC>>>(m128);
    phase3_kernel<<<dim3(NCH, BB), CC>>>(ts, labels, amounts, out);
}

// round 17
// speedup vs baseline: 1.0576x; 1.0576x over previous
#include <cuda_runtime.h>
#include <cuda_bf16.h>

// Problem constants (match reference_code)
#define BB   32
#define LL   4096
#define CC   128
#define CS   64             // chunk size along L (halved: R14 ncu showed phase1/3 serial-latency-bound)
#define NCH  (LL / CS)      // 64 chunks per batch
#define NCARRY (NCH - 1)    // 63 carries consumed (last chunk's is dead)
#define OUTW (2 * CC + 1)   // 257 output features
#define TROWS 16            // output rows staged in smem per flush

// Scratch: end-of-chunk carry states for chunks 0..NCARRY-1
__device__ float g_cP[BB * NCARRY * CC];   // one-hot EMA state per channel
__device__ float g_cA[BB * NCARRY * CC];   // amount*one-hot EMA state per channel
__device__ float g_cD[BB * NCARRY];        // delta EMA state

// ---------------------------------------------------------------------------
// Phase 1: per-chunk local recurrence from zero init (chunk 0: exact init).
// Grid (NCARRY, BB), 128 threads (one channel per thread), 64 serial steps.
// Bit-faithful to the reference's iterated recurrence within the chunk.
// No prob-sum state: fmaf(0.9f,1.0f,0.1f) rounds to exactly 1.0f, so the
// sum-EMA is constant 1.0 and normalization is a no-op (ref drift <= ~6e-7).
// ---------------------------------------------------------------------------
__global__ __launch_bounds__(CC) void phase1_kernel(
    const float* __restrict__ ts,
    const int*   __restrict__ labels,
    const float* __restrict__ amounts)
{
    const int b  = blockIdx.y;
    const int ch = blockIdx.x;
    const int c  = threadIdx.x;

    __shared__ int   slab[CS];
    __shared__ float samt[CS];
    __shared__ float sdel[CS];

    if (c < CS) {
        const int gl = b * LL + ch * CS + c;
        slab[c] = labels[gl];
        samt[c] = amounts[gl];
        float del = 0.f;
        if (!(ch == 0 && c == 0)) {       // guard avoids OOB read at global l==0
            del = fminf(ts[gl] - ts[gl - 1], 100.0f);
        }
        sdel[c] = del;
    }
    __syncthreads();

    float p = 0.f, a = 0.f, d = 0.f;
    int l0 = 0;
    if (ch == 0) {
        // exact init: y[0] = x[0]
        const int   lab = slab[0];
        const float oh  = (lab == c) ? 1.0f : 0.0f;
        p = oh;
        a = samt[0] * oh;
        d = 0.0f;
        l0 = 1;
    }

    #pragma unroll 4
    for (int l = l0; l < CS; l++) {
        const int   lab  = slab[l];
        const float incp = (lab == c) ? 0.1f : 0.0f;
        p = fmaf(0.9f, p, incp);
        a = fmaf(0.9f, a, incp * samt[l]);
        d = fmaf(0.9f, d, 0.1f * sdel[l]);
    }

    const int idx = b * NCARRY + ch;
    g_cP[idx * CC + c] = p;
    g_cA[idx * CC + c] = a;
    if (c == 0) {
        g_cD[idx] = d;
    }
}

// ---------------------------------------------------------------------------
// Phase 2: convert chunk-local states to full prefix states (in place).
// full[k] = m^CS * full[k-1] + local[k].  Grid (BB, 3), 128 threads.
// blockIdx.y selects the array (0=P, 1=A, 2=D) so each branch keeps only
// ~63 live registers (no spill). Load-all first (63 independent LDGs ->
// MLP hides one DRAM latency), then the FMA chain, then store-all.
// ---------------------------------------------------------------------------
__global__ __launch_bounds__(CC) void phase2_kernel(float mCS)
{
    const int b = blockIdx.x;
    const int c = threadIdx.x;
    const int which = blockIdx.y;
    const int base = b * NCARRY;

    if (which == 0) {
        float v[NCARRY];
        #pragma unroll
        for (int k = 0; k < NCARRY; k++) v[k] = g_cP[(base + k) * CC + c];
        #pragma unroll
        for (int k = 1; k < NCARRY; k++) v[k] = fmaf(mCS, v[k - 1], v[k]);
        #pragma unroll
        for (int k = 1; k < NCARRY; k++) g_cP[(base + k) * CC + c] = v[k];
    } else if (which == 1) {
        float v[NCARRY];
        #pragma unroll
        for (int k = 0; k < NCARRY; k++) v[k] = g_cA[(base + k) * CC + c];
        #pragma unroll
        for (int k = 1; k < NCARRY; k++) v[k] = fmaf(mCS, v[k - 1], v[k]);
        #pragma unroll
        for (int k = 1; k < NCARRY; k++) g_cA[(base + k) * CC + c] = v[k];
    } else if (c == 0) {
        float v[NCARRY];
        #pragma unroll
        for (int k = 0; k < NCARRY; k++) v[k] = g_cD[base + k];
        #pragma unroll
        for (int k = 1; k < NCARRY; k++) v[k] = fmaf(mCS, v[k - 1], v[k]);
        #pragma unroll
        for (int k = 1; k < NCARRY; k++) g_cD[base + k] = v[k];
    }
}

// ---------------------------------------------------------------------------
// Phase 3: per-chunk recurrence seeded with the exact carry; emit all outputs.
// probs emitted unnormalized (division by the sum-EMA == 1.0f is a no-op);
// amt = a / max(p, 1e-6) -> single MUFU.RCP per thread-step.
// Outputs staged in smem TROWS-row tiles, flushed as float4 (STG.128): chunk
// base is ch*64*257*4 B = ch*65792 B (mod 16 == 0) and each 16-row tile is
// 16448 B (mod 16 == 0), so alignment holds despite the odd 257-float row.
// Grid (NCH, BB) = 2048 blocks, 128 threads, 64 serial steps per block.
// ---------------------------------------------------------------------------
__global__ __launch_bounds__(CC) void phase3_kernel(
    const float* __restrict__ ts,
    const int*   __restrict__ labels,
    const float* __restrict__ amounts,
    float*       __restrict__ out)
{
    const int b  = blockIdx.y;
    const int ch = blockIdx.x;
    const int c  = threadIdx.x;

    __shared__ int   slab[CS];
    __shared__ float samt[CS];
    __shared__ float sdel[CS];
    __shared__ __align__(16) float stile[TROWS * OUTW];  // 16*257 floats = 16448 B

    if (c < CS) {
        const int gl = b * LL + ch * CS + c;
        slab[c] = labels[gl];
        samt[c] = amounts[gl];
        float del = 0.f;
        if (!(ch == 0 && c == 0)) {
            del = fminf(ts[gl] - ts[gl - 1], 100.0f);
        }
        sdel[c] = del;
    }

    float p, a, d;
    if (ch == 0) {
        p = 0.f; a = 0.f; d = 0.f;
    } else {
        const int idx = b * NCARRY + ch - 1;  // full state at end of previous chunk
        p = g_cP[idx * CC + c];
        a = g_cA[idx * CC + c];
        d = g_cD[idx];
    }
    __syncthreads();

    float* ob = out + (size_t)(b * LL + ch * CS) * OUTW;
    const bool first_chunk = (ch == 0);

    for (int t0 = 0; t0 < CS; t0 += TROWS) {
        // compute TROWS steps into the smem tile
        #pragma unroll 4
        for (int l = t0; l < t0 + TROWS; l++) {
            if (first_chunk && l == 0) {
                // exact init: y[0] = x[0]
                const int   lab = slab[0];
                const float oh  = (lab == c) ? 1.0f : 0.0f;
                p = oh;
                a = samt[0] * oh;
                d = 0.0f;
            } else {
                const int   lab  = slab[l];
                const float incp = (lab == c) ? 0.1f : 0.0f;
                p = fmaf(0.9f, p, incp);
                a = fmaf(0.9f, a, incp * samt[l]);
                d = fmaf(0.9f, d, 0.1f * sdel[l]);
            }
            const float ao = __fdividef(a, fmaxf(p, 1e-6f));
            float* row = stile + (l - t0) * OUTW;
            row[1 + c]      = p;     // normalized prob == p (sum == 1)
            row[1 + CC + c] = ao;
            if (c == 0) row[0] = d;
        }
        __syncthreads();

        // flush tile: TROWS*OUTW floats = 1028 float4s, contiguous & 16B-aligned
        {
            const float4* src = (const float4*)stile;
            float4* dst = (float4*)(ob + (size_t)t0 * OUTW);
            #pragma unroll
            for (int i = c; i < (TROWS * OUTW) / 4; i += CC) {
                dst[i] = src[i];
            }
        }
        __syncthreads();
    }
}

// ---------------------------------------------------------------------------
// Launch: three dependent kernels on the capture stream. No allocs, no syncs.
// ---------------------------------------------------------------------------
extern "C" void kernel_launch(void* const* d_in, const int* in_sizes, int n_in,
                              void* d_out, int out_size)
{
    const float* ts      = (const float*)d_in[0];
    const int*   labels  = (const int*)  d_in[1];
    const float* amounts = (const float*)d_in[2];
    float*       out     = (float*)d_out;

    // m^CS computed in double on host (deterministic)
    double x = 1.0;
    for (int i = 0; i < CS; i++) x *= 0.9;
    const float mCS = (float)x;

    phase1_kernel<<<dim3(NCARRY, BB), CC>>>(ts, labels, amounts);
    phase2_kernel<<<dim3(BB, 3), CC>>>(mCS);
    phase3_kernel<<<dim3(NCH, BB), CC>>>(ts, labels, amounts, out);
}